// round 15
// baseline (speedup 1.0000x reference)
#include <cuda_runtime.h>
#include <math_constants.h>
#include <cstdint>

// B=8, U=V=13 (UV=169), H=128, W=160 (HW=20480), TRUNC=4, disp -6..6
#define UV 169
#define VD 13
#define HW 20480
#define PIX 32                    // pixels per chunk (128B per plane)
#define NT 256                    // 8 threads per pixel
#define RS 32                     // unpadded row; banks decorrelated via XOR swizzle
#define BUF (UV * RS)             // 5408 floats per buffer
#define GUARD 128                 // 4 rows guard each side (pass B v-overhang)
#define SMEM_FLOATS (2 * GUARD + 2 * BUF)       // 11072
#define SMEM_BYTES (SMEM_FLOATS * 4)            // 44288 B -> 5 CTAs/SM
#define CHUNKS_PER_B (HW / PIX)   // 640
#define NCHUNKS (8 * CHUNKS_PER_B)  // 5120
#define L2E 1.4426950408889634f
#define NEGBIG (-1e30f)

// float-index swizzle: row uv (32 floats), column c -> c ^ ((uv&7)<<2)
#define SWZ(uvi, c) (((uvi) * RS) + ((c) ^ ((((unsigned)(uvi)) & 7u) << 2)))

__device__ __forceinline__ void cp_async16(unsigned int dst, const float* src) {
    asm volatile("cp.async.cg.shared.global [%0], [%1], 16;" :: "r"(dst), "l"(src) : "memory");
}
__device__ __forceinline__ void cp_commit() {
    asm volatile("cp.async.commit_group;" ::: "memory");
}
template<int N>
__device__ __forceinline__ void cp_wait() {
    asm volatile("cp.async.wait_group %0;" :: "n"(N) : "memory");
}
__device__ __forceinline__ float ex2f(float t) {
    float r;
    asm("ex2.approx.f32 %0, %1;" : "=f"(r) : "f"(t));
    return r;
}

__global__ __launch_bounds__(NT, 5)   // 5 CTAs/SM -> 51-reg budget
void flow_regression_kernel(const float* __restrict__ x, float* __restrict__ out) {
    extern __shared__ float s_raw[];
    float* s0 = s_raw + GUARD;        // buffer 0 base; buffer nb at s0 + nb*BUF
    const int tid = threadIdx.x;
    const int bid = blockIdx.x;
    const int G   = gridDim.x;
    const unsigned int sbase0 = (unsigned int)__cvta_generic_to_shared(s0);

    const int sub = tid & 7;          // eighth of per-pixel work
    const int p   = tid >> 3;         // pixel 0..31

    // load mapping: line tid -> (plane0 = tid>>3, 16B slot q = tid&7)
    // plane advances by 32 per step -> (plane&7) constant -> swizzle folds into base.
    const int plane0 = tid >> 3;
    const int qs0    = ((tid & 7) * 4) ^ ((plane0 & 7) << 2);   // swizzled float col

    auto issue_load = [&](int g, int nb) {
        int b  = g / CHUNKS_PER_B;
        int ch = g - b * CHUNKS_PER_B;
        const float* gp = x + (size_t)b * (UV * HW) + ch * PIX + plane0 * HW + (tid & 7) * 4;
        unsigned int dst = sbase0 + (unsigned int)(nb * BUF + plane0 * RS + qs0) * 4u;
        #pragma unroll
        for (int k = 0; k < 5; k++) {                 // lines tid + 256k (1280)
            cp_async16(dst, gp);
            gp  += 32 * HW;
            dst += 32 * RS * 4;
        }
        if (tid < 72) cp_async16(dst, gp);            // planes 160..168 (same swizzle const)
        cp_commit();
    };

    issue_load(bid, 0);
    int nb = 0;

    for (int g = bid; g < NCHUNKS; g += G) {
        cp_wait<0>();
        __syncthreads();              // buffer nb visible; reads of nb^1 all finished
        if (g + G < NCHUNKS) issue_load(g + G, nb ^ 1);   // overlaps compute below

        const float* sp = s0 + nb * BUF;

        // ---- Pass A: argmax over 169, 8-way split, 2 independent chains ----
        // uv = sub + 8t  ->  (uv&7)==sub  ->  swizzled column constant per thread
        const int pcol = p ^ (sub << 2);
        float mA = -CUDART_INF_F, mB = -CUDART_INF_F;
        int   aA = 0, aB = 0;
        {
            const float* r = sp + sub * RS + pcol;
            #pragma unroll
            for (int t = 0; t < 21; t += 2) {         // even t -> chain A
                float v = r[t * 8 * RS];
                int uv = sub + 8 * t;
                if (v > mA) { mA = v; aA = uv; }
            }
            #pragma unroll
            for (int t = 1; t < 21; t += 2) {         // odd t -> chain B
                float v = r[t * 8 * RS];
                int uv = sub + 8 * t;
                if (v > mB) { mB = v; aB = uv; }
            }
            if (sub == 0) {                           // uv=168: (168&7)==0 == sub
                float v = r[168 * RS];
                if (v > mB) { mB = v; aB = 168; }
            }
        }
        float m; int am;
        if (mB > mA || (mB == mA && aB < aA)) { m = mB; am = aB; }
        else                                  { m = mA; am = aA; }

        #pragma unroll
        for (int off = 1; off <= 4; off <<= 1) {
            float mo = __shfl_xor_sync(0xffffffffu, m,  off);
            int   ao = __shfl_xor_sync(0xffffffffu, am, off);
            if (mo > m || (mo == m && ao < am)) { m = mo; am = ao; }
        }
        const int ui = am / VD;
        const int vi = am - ui * VD;
        const float cc = m * L2E;                  // exp(x-m) = ex2(x*L2E - cc)

        // ---- Pass B (row-based): thread owns row du=sub-4; row du=+4 distributed ----
        unsigned int vmV = 0x1FFu;                 // v = vi-4+j valid iff 0<=v<=12
        if (vi < 4) vmV &= (0x1FFu << (4 - vi));
        if (vi > 8) vmV &= (0x1FFu >> (vi - 8));

        const int u   = ui + sub - 4;
        const bool oku = (unsigned)u <= 12u;
        const int uc  = min(max(u, 0), 12);
        const float wu = (float)(u - 6);
        const unsigned int vm = oku ? vmV : 0u;

        float Zb = 0.0f, Zx = 0.0f, T = 0.0f;      // T = sum e*j
        {
            const int uvb = uc * VD + vi - 4;      // j=0 row index (may underflow into guard)
            #pragma unroll
            for (int j = 0; j < 9; j++) {
                float a = (vm & (1u << j)) ? sp[SWZ(uvb + j, p)] : NEGBIG;
                float e = ex2f(fmaf(a, L2E, -cc));
                Zb += e;
                T = fmaf(e, (float)j, T);
            }
        }
        const int u4 = ui + 4;
        const bool ok4 = (u4 <= 12);
        const int uc4 = min(u4, 12);
        const float wu4 = (float)(u4 - 6);
        {
            const int uvb4 = uc4 * VD + vi - 4;
            bool oke = ok4 && ((vmV >> sub) & 1u);
            float a1 = oke ? sp[SWZ(uvb4 + sub, p)] : NEGBIG;
            float e1 = ex2f(fmaf(a1, L2E, -cc));
            Zx += e1;
            T = fmaf(e1, (float)sub, T);

            bool oke8 = ok4 && (sub == 0) && ((vmV >> 8) & 1u);
            float a2 = oke8 ? sp[SWZ(uvb4 + 8, p)] : NEGBIG;
            float e2 = ex2f(fmaf(a2, L2E, -cc));
            Zx += e2;
            T = fmaf(e2, 8.0f, T);
        }

        float Z  = Zb + Zx;
        float sU = fmaf(wu, Zb, wu4 * Zx);
        #pragma unroll
        for (int off = 1; off <= 4; off <<= 1) {
            Z  += __shfl_xor_sync(0xffffffffu, Z,  off);
            sU += __shfl_xor_sync(0xffffffffu, sU, off);
            T  += __shfl_xor_sync(0xffffffffu, T,  off);
        }

        if (sub == 0) {
            const int b  = g / CHUNKS_PER_B;
            const int ch = g - b * CHUNKS_PER_B;
            const float inv = __frcp_rn(Z);
            const float sV = fmaf((float)(vi - 10), Z, T);   // wv = (vi-10)+j
            const int pix = ch * PIX + p;
            out[(b * 2 + 0) * HW + pix] = sU * inv;
            out[(b * 2 + 1) * HW + pix] = sV * inv;
        }
        nb ^= 1;
        // next iteration's __syncthreads orders these reads before refill
    }
}

extern "C" void kernel_launch(void* const* d_in, const int* in_sizes, int n_in,
                              void* d_out, int out_size) {
    (void)in_sizes; (void)n_in; (void)out_size;
    const float* x = (const float*)d_in[0];
    float* out = (float*)d_out;

    static int nsm = 0;
    if (nsm == 0) {
        cudaDeviceGetAttribute(&nsm, cudaDevAttrMultiProcessorCount, 0);
        if (nsm <= 0) nsm = 148;
        cudaFuncSetAttribute(flow_regression_kernel,
                             cudaFuncAttributeMaxDynamicSharedMemorySize, SMEM_BYTES);
        cudaFuncSetAttribute(flow_regression_kernel,
                             cudaFuncAttributePreferredSharedMemoryCarveout, 100);
    }

    const int nblocks = 5 * nsm;      // persistent: 5 CTAs per SM
    flow_regression_kernel<<<nblocks, NT, SMEM_BYTES>>>(x, out);
}

// round 16
// speedup vs baseline: 1.1905x; 1.1905x over previous
#include <cuda_runtime.h>
#include <math_constants.h>
#include <cstdint>

// B=8, U=V=13 (UV=169), H=128, W=160 (HW=20480), TRUNC=4, disp -6..6
#define UV 169
#define VD 13
#define HW 20480
#define PIX 32                    // pixels per chunk (128B per plane)
#define NT 128                    // 4 threads per pixel
#define RS 32                     // unpadded row; banks decorrelated via XOR swizzle
#define BUF (UV * RS)             // 5408 floats per buffer
#define GUARD 128                 // 4 rows guard each side (pass B overhang)
#define SMEM_FLOATS (2 * GUARD + 2 * BUF)       // 11072
#define SMEM_BYTES (SMEM_FLOATS * 4)            // 44288 B -> 5 CTAs/SM
#define CHUNKS_PER_B (HW / PIX)   // 640
#define NCHUNKS (8 * CHUNKS_PER_B)  // 5120
#define L2E 1.4426950408889634f
#define NEGBIG (-1e30f)

__device__ __forceinline__ void cp_async16(unsigned int dst, const float* src) {
    asm volatile("cp.async.cg.shared.global [%0], [%1], 16;" :: "r"(dst), "l"(src) : "memory");
}
__device__ __forceinline__ void cp_commit() {
    asm volatile("cp.async.commit_group;" ::: "memory");
}
template<int N>
__device__ __forceinline__ void cp_wait() {
    asm volatile("cp.async.wait_group %0;" :: "n"(N) : "memory");
}
__device__ __forceinline__ float ex2f(float t) {
    float r;
    asm("ex2.approx.f32 %0, %1;" : "=f"(r) : "f"(t));
    return r;
}

__global__ __launch_bounds__(NT, 5)
void flow_regression_kernel(const float* __restrict__ x, float* __restrict__ out) {
    extern __shared__ float s_raw[];
    float* s0 = s_raw + GUARD;        // buffer 0 base; buffer nb at s0 + nb*BUF
    const int tid = threadIdx.x;
    const int bid = blockIdx.x;
    const int G   = gridDim.x;
    const unsigned int sbase0 = (unsigned int)__cvta_generic_to_shared(s0);

    const int sub = tid & 3;          // quarter of per-pixel work
    const int p   = tid >> 2;         // pixel 0..31

    // load mapping: line = tid + 128k; plane = line>>3, q = line&7.
    // plane step per k = 16 (== 0 mod 4) -> swizzle constant folds into base.
    const int plane0 = tid >> 3;      // 0..15
    const int q0     = (tid & 7) * 4;
    const int qs0    = q0 ^ ((plane0 & 3) << 3);   // swizzled float col

    auto issue_load = [&](int g, int nb) {
        int b  = g / CHUNKS_PER_B;
        int ch = g - b * CHUNKS_PER_B;
        const float* gp = x + (size_t)b * (UV * HW) + ch * PIX + plane0 * HW + q0;
        unsigned int dst = sbase0 + (unsigned int)(nb * BUF + plane0 * RS + qs0) * 4u;
        #pragma unroll
        for (int k = 0; k < 10; k++) {                // lines tid + 128k (1280)
            cp_async16(dst, gp);
            gp  += 16 * HW;
            dst += 16 * RS * 4;
        }
        if (tid < 72) cp_async16(dst, gp);            // planes 160..168
        cp_commit();
    };

    issue_load(bid, 0);
    int nb = 0;

    for (int g = bid; g < NCHUNKS; g += G) {
        cp_wait<0>();
        __syncthreads();              // buffer nb visible; reads of nb^1 all finished
        if (g + G < NCHUNKS) issue_load(g + G, nb ^ 1);   // overlaps compute below

        const float* sp = s0 + nb * BUF;

        // ---- Pass A: argmax over 169, 4-way split, 2 chains (ties -> lowest uv) ----
        // uv = sub + 4t  ->  (uv&3)==sub  ->  swizzled column constant per thread
        const int pcol = p ^ (sub << 3);
        float mA = -CUDART_INF_F, mB = -CUDART_INF_F;
        int   aA = 0, aB = 0;
        {
            const float* r = sp + sub * RS + pcol;
            #pragma unroll
            for (int t = 0; t < 42; t += 2) {         // even t -> chain A (21)
                float v = r[t * 4 * RS];
                int uv = sub + 4 * t;
                if (v > mA) { mA = v; aA = uv; }
            }
            #pragma unroll
            for (int t = 1; t < 42; t += 2) {         // odd t -> chain B (21)
                float v = r[t * 4 * RS];
                int uv = sub + 4 * t;
                if (v > mB) { mB = v; aB = uv; }
            }
            if (sub == 0) {                           // uv=168: 168&3==0==sub
                float v = r[168 * RS];
                if (v > mB) { mB = v; aB = 168; }
            }
        }
        float m; int am;
        if (mB > mA || (mB == mA && aB < aA)) { m = mB; am = aB; }
        else                                  { m = mA; am = aA; }

        #pragma unroll
        for (int off = 1; off <= 2; off <<= 1) {
            float mo = __shfl_xor_sync(0xffffffffu, m,  off);
            int   ao = __shfl_xor_sync(0xffffffffu, am, off);
            if (mo > m || (mo == m && ao < am)) { m = mo; am = ao; }
        }
        const int ui = am / VD;
        const int vi = am - ui * VD;
        const float cc = m * L2E;                  // exp(x-m) = ex2(x*L2E - cc)

        // ---- Pass B: 9x9 window. Thread owns base rows du8 = sub, sub+4; row 8 split. ----
        unsigned int vmV = 0x1FFu;                 // v = vi-4+j valid iff 0<=v<=12
        if (vi < 4) vmV &= (0x1FFu << (4 - vi));
        if (vi > 8) vmV &= (0x1FFu >> (vi - 8));

        float Z = 0.0f, T = 0.0f, sU = 0.0f;       // T = sum e*j
        #pragma unroll
        for (int rr = 0; rr < 2; rr++) {
            const int r8 = sub + rr * 4;           // du8 in 0..7
            const int u  = ui + r8 - 4;
            const bool oku = (unsigned)u <= 12u;
            const int uc = min(max(u, 0), 12);
            const unsigned int vm = oku ? vmV : 0u;
            const float wu = (float)(u - 6);
            const int uvb = uc * VD + vi - 4;      // guards absorb +/- overhang
            float Zr = 0.0f;
            #pragma unroll
            for (int j = 0; j < 9; j++) {
                int row = uvb + j;
                int col = p ^ ((row & 3) << 3);
                float a = (vm & (1u << j)) ? sp[row * RS + col] : NEGBIG;
                float e = ex2f(fmaf(a, L2E, -cc));
                Zr += e;
                T = fmaf(e, (float)j, T);
            }
            Z += Zr;
            sU = fmaf(wu, Zr, sU);
        }
        {   // extra row du=+4: j = sub, sub+4 on all subs; j=8 on sub0
            const int u4 = ui + 4;
            const bool ok4 = (u4 <= 12);
            const int uc4 = min(u4, 12);
            const int uvb4 = uc4 * VD + vi - 4;
            float Z4 = 0.0f;
            {
                int j = sub, row = uvb4 + j;
                int col = p ^ ((row & 3) << 3);
                bool ok = ok4 && ((vmV >> j) & 1u);
                float a = ok ? sp[row * RS + col] : NEGBIG;
                float e = ex2f(fmaf(a, L2E, -cc));
                Z4 += e; T = fmaf(e, (float)j, T);
            }
            {
                int j = sub + 4, row = uvb4 + j;
                int col = p ^ ((row & 3) << 3);
                bool ok = ok4 && ((vmV >> j) & 1u);
                float a = ok ? sp[row * RS + col] : NEGBIG;
                float e = ex2f(fmaf(a, L2E, -cc));
                Z4 += e; T = fmaf(e, (float)j, T);
            }
            {
                int row = uvb4 + 8;
                int col = p ^ ((row & 3) << 3);
                bool ok = ok4 && (sub == 0) && ((vmV >> 8) & 1u);
                float a = ok ? sp[row * RS + col] : NEGBIG;
                float e = ex2f(fmaf(a, L2E, -cc));
                Z4 += e; T = fmaf(e, 8.0f, T);
            }
            Z += Z4;
            sU = fmaf((float)(u4 - 6), Z4, sU);
        }

        #pragma unroll
        for (int off = 1; off <= 2; off <<= 1) {
            Z  += __shfl_xor_sync(0xffffffffu, Z,  off);
            sU += __shfl_xor_sync(0xffffffffu, sU, off);
            T  += __shfl_xor_sync(0xffffffffu, T,  off);
        }

        if (sub == 0) {
            const int b  = g / CHUNKS_PER_B;
            const int ch = g - b * CHUNKS_PER_B;
            const float inv = __frcp_rn(Z);
            const float sV = fmaf((float)(vi - 10), Z, T);   // wv = (vi-10)+j
            const int pix = ch * PIX + p;
            out[(b * 2 + 0) * HW + pix] = sU * inv;
            out[(b * 2 + 1) * HW + pix] = sV * inv;
        }
        nb ^= 1;
        // next iteration's __syncthreads orders these reads before refill
    }
}

extern "C" void kernel_launch(void* const* d_in, const int* in_sizes, int n_in,
                              void* d_out, int out_size) {
    (void)in_sizes; (void)n_in; (void)out_size;
    const float* x = (const float*)d_in[0];
    float* out = (float*)d_out;

    static int nsm = 0;
    if (nsm == 0) {
        cudaDeviceGetAttribute(&nsm, cudaDevAttrMultiProcessorCount, 0);
        if (nsm <= 0) nsm = 148;
        cudaFuncSetAttribute(flow_regression_kernel,
                             cudaFuncAttributeMaxDynamicSharedMemorySize, SMEM_BYTES);
        cudaFuncSetAttribute(flow_regression_kernel,
                             cudaFuncAttributePreferredSharedMemoryCarveout, 100);
    }

    const int nblocks = 5 * nsm;      // persistent: 5 CTAs per SM
    flow_regression_kernel<<<nblocks, NT, SMEM_BYTES>>>(x, out);
}